// round 16
// baseline (speedup 1.0000x reference)
#include <cuda_runtime.h>
#include <cuda_fp16.h>
#include <cstdint>

#define BATCH 2
#define SEQ   2048
#define DIM   1024
#define NH    16
#define HD    64
#define MTOT  (BATCH*SEQ)   // 4096

// ---------------- scratch (device globals; no allocation allowed) ----------
__device__ uint32_t g_xh[MTOT*DIM/2];          // x fp16 pairs
__device__ uint32_t g_wh[4][DIM*DIM/2];        // wq,wk,wv,wo fp16 pairs
__device__ uint32_t g_qh[BATCH*NH*SEQ*HD/2];   // Q fp16 pairs [b][h][s][hd], pre-scaled log2e/8
__device__ uint32_t g_kh[BATCH*NH*SEQ*HD/2];   // K fp16 pairs [b][h][s][hd]
__device__ __half   g_vh[BATCH*NH*SEQ*HD];     // V fp16 TRANSPOSED [b][h][hd][s]
__device__ uint32_t g_ch[MTOT*DIM/2];          // ctx fp16 pairs

// ---------------- helpers ---------------------------------------------------
__device__ __forceinline__ uint32_t pack_f16(float lo, float hi) {
    uint32_t r;
    asm("cvt.rn.f16x2.f32 %0, %1, %2;" : "=r"(r) : "f"(hi), "f"(lo));
    return r;
}
__device__ __forceinline__ float ex2(float x) {
    float y;
    asm("ex2.approx.ftz.f32 %0, %1;" : "=f"(y) : "f"(x));
    return y;
}
__device__ __forceinline__ uint32_t smaddr(const void* p) {
    return (uint32_t)__cvta_generic_to_shared(p);
}
#define CPA16(dst, src) \
    asm volatile("cp.async.cg.shared.global [%0], [%1], 16;" :: "r"(dst), "l"(src))
#define CPA_COMMIT() asm volatile("cp.async.commit_group;")
#define CPA_WAIT(n)  asm volatile("cp.async.wait_group %0;" :: "n"(n))

__device__ __forceinline__ void ldsm4(uint32_t& r0, uint32_t& r1,
                                      uint32_t& r2, uint32_t& r3, uint32_t a) {
    asm volatile("ldmatrix.sync.aligned.m8n8.x4.shared.b16 {%0,%1,%2,%3}, [%4];"
                 : "=r"(r0), "=r"(r1), "=r"(r2), "=r"(r3) : "r"(a));
}

// fp16 m16n8k16
__device__ __forceinline__ void mma16(float* c,
    uint32_t a0, uint32_t a1, uint32_t a2, uint32_t a3,
    uint32_t b0, uint32_t b1)
{
    asm volatile(
        "mma.sync.aligned.m16n8k16.row.col.f32.f16.f16.f32 "
        "{%0,%1,%2,%3}, {%4,%5,%6,%7}, {%8,%9}, {%0,%1,%2,%3};"
        : "+f"(c[0]), "+f"(c[1]), "+f"(c[2]), "+f"(c[3])
        : "r"(a0), "r"(a1), "r"(a2), "r"(a3), "r"(b0), "r"(b1));
}

// ---------------- conversion kernel: fp32 -> fp16 ---------------------------
__global__ void cvt_kernel(const float* __restrict__ x,
                           const float* __restrict__ w0,
                           const float* __restrict__ w1,
                           const float* __restrict__ w2,
                           const float* __restrict__ w3)
{
    int z = blockIdx.y;
    const float* src;
    uint32_t* dst;
    int n4;
    if (z == 0) { src = x; dst = g_xh; n4 = MTOT*DIM/4; }
    else {
        src = (z == 1) ? w0 : (z == 2) ? w1 : (z == 3) ? w2 : w3;
        dst = g_wh[z-1];
        n4 = DIM*DIM/4;
    }
    int i = blockIdx.x * blockDim.x + threadIdx.x;
    if (i >= n4) return;
    float4 v = ((const float4*)src)[i];
    ((uint2*)dst)[i] = make_uint2(pack_f16(v.x, v.y), pack_f16(v.z, v.w));
}

// ---------------- fp16 projection GEMM: 128x128 CTA, 4 warps (64x64 tile) --
// Fat warp tiles: 8 ldsm per 32 mma, 128 independent accumulators per warp.
// 128 thr/CTA, 2 CTAs/SM.
#define MT    128
#define NT    128
#define KC    64
#define RSTB  144                       // smem row stride bytes
#define A_STB (MT*RSTB)                 // 18432 B
#define B_STB (NT*RSTB)                 // 18432 B
#define STG_B (A_STB + B_STB)           // 36864 B
#define NSTG  3
#define PROJ_SMEM (NSTG*STG_B)          // 110592 B

__device__ __forceinline__ void proj_loads(const char* gA, const char* gW,
                                           int kByte, char* smA, char* smB,
                                           int tid)
{
    #pragma unroll
    for (int i = 0; i < 8; i++) {        // A: 128 rows x 8 16B chunks = 1024
        int idx = tid + i*128;
        int r = idx >> 3, c = (idx & 7) << 4;
        CPA16(smaddr(smA + r*RSTB + c), gA + (size_t)r*(DIM*2) + kByte + c);
    }
    #pragma unroll
    for (int i = 0; i < 8; i++) {        // B: 128 rows x 8 16B chunks = 1024
        int idx = tid + i*128;
        int r = idx >> 3, c = (idx & 7) << 4;
        CPA16(smaddr(smB + r*RSTB + c), gW + (size_t)r*(DIM*2) + kByte + c);
    }
}

__device__ __forceinline__ void gemm_main(
    const uint32_t* __restrict__ A, const uint32_t* __restrict__ W,
    int mBase, int nBase, float c[4][8][4], char* sm)
{
    int tid  = threadIdx.x;
    int lane = tid & 31, warp = tid >> 5;
    int wm = (warp & 1) * 64;
    int wn = (warp >> 1) * 64;

    const char* gA = (const char*)A + (size_t)mBase * (DIM*2);
    const char* gB = (const char*)W + (size_t)nBase * (DIM*2);

    int l15 = lane & 15, lh = (lane >> 4) << 4;

    proj_loads(gA, gB, 0,     sm,         sm + A_STB,         tid);
    CPA_COMMIT();
    proj_loads(gA, gB, KC*2,  sm + STG_B, sm + STG_B + A_STB, tid);
    CPA_COMMIT();

    const int nCh = DIM / KC;   // 16
    int stg = 0;
    for (int it = 0; it < nCh; it++) {
        if (it == nCh - 1) { CPA_WAIT(0); } else { CPA_WAIT(1); }
        __syncthreads();
        if (it + 2 < nCh) {
            int ls = stg + 2; if (ls >= NSTG) ls -= NSTG;
            char* base = sm + ls*STG_B;
            proj_loads(gA, gB, (it+2)*KC*2, base, base + A_STB, tid);
            CPA_COMMIT();
        }
        char* as = sm + stg*STG_B;
        char* bs = as + A_STB;
        #pragma unroll
        for (int ksl = 0; ksl < 4; ksl++) {   // 4 k16-steps per chunk
            uint32_t a[4][4], b[4][4];
            #pragma unroll
            for (int mf = 0; mf < 4; mf++)
                ldsm4(a[mf][0], a[mf][1], a[mf][2], a[mf][3],
                      smaddr(as + (wm + mf*16 + l15)*RSTB + lh + ksl*32));
            #pragma unroll
            for (int p = 0; p < 4; p++)
                ldsm4(b[p][0], b[p][1], b[p][2], b[p][3],
                      smaddr(bs + (wn + p*16 + l15)*RSTB + lh + ksl*32));
            #pragma unroll
            for (int p = 0; p < 4; p++)
                #pragma unroll
                for (int mf = 0; mf < 4; mf++) {
                    mma16(c[mf][2*p],   a[mf][0], a[mf][1], a[mf][2], a[mf][3],
                          b[p][0], b[p][2]);
                    mma16(c[mf][2*p+1], a[mf][0], a[mf][1], a[mf][2], a[mf][3],
                          b[p][1], b[p][3]);
                }
        }
        if (++stg == NSTG) stg = 0;
    }
}

// ---------------- QKV projection -------------------------------------------
#define QSCALE 0.18033688011112042f    // 0.125 * log2(e)

__global__ void __launch_bounds__(128, 2) qkv_tc()
{
    extern __shared__ char sm[];
    int z = blockIdx.z;
    const uint32_t* W = g_wh[z];
    float scale = (z == 0) ? QSCALE : 1.0f;

    float c[4][8][4];
    #pragma unroll
    for (int mf = 0; mf < 4; mf++)
        #pragma unroll
        for (int nf = 0; nf < 8; nf++)
            #pragma unroll
            for (int i = 0; i < 4; i++) c[mf][nf][i] = 0.f;

    int mBase = blockIdx.y * MT, nBase = blockIdx.x * NT;
    gemm_main(g_xh, W, mBase, nBase, c, sm);

    int tid = threadIdx.x, lane = tid & 31, warp = tid >> 5;
    int g = lane >> 2, t = lane & 3;
    int wm = (warp & 1) * 64, wn = (warp >> 1) * 64;

    if (z != 2) {
        // Q/K: fp16 pairs [b][h][s][hd]
        uint32_t* Out = (z == 0) ? g_qh : g_kh;
        #pragma unroll
        for (int mf = 0; mf < 4; mf++) {
            int m = mBase + wm + mf*16 + g;
            int b = m >> 11;
            int s = m & (SEQ - 1);
            #pragma unroll
            for (int nf = 0; nf < 8; nf++) {
                int n = nBase + wn + nf*8 + 2*t;
                int h = n >> 6, hd0 = n & 63;
                uint32_t* dst = Out + (((size_t)((b*NH + h)*SEQ + s))*HD + hd0) / 2;
                dst[0]        = pack_f16(c[mf][nf][0]*scale, c[mf][nf][1]*scale);
                dst[8*HD/2]   = pack_f16(c[mf][nf][2]*scale, c[mf][nf][3]*scale);
            }
        }
    } else {
        // V: fp16 transposed [b][h][hd][s]
        #pragma unroll
        for (int mf = 0; mf < 4; mf++) {
            int m = mBase + wm + mf*16 + g;
            int b = m >> 11;
            int s = m & (SEQ - 1);
            #pragma unroll
            for (int nf = 0; nf < 8; nf++) {
                int n = nBase + wn + nf*8 + 2*t;
                int h = n >> 6, hd = n & 63;
                __half* base = g_vh + ((size_t)((b*NH + h)*HD + hd))*SEQ + s;
                base[0]       = __float2half_rn(c[mf][nf][0]);
                base[8]       = __float2half_rn(c[mf][nf][2]);
                base[SEQ]     = __float2half_rn(c[mf][nf][1]);
                base[SEQ + 8] = __float2half_rn(c[mf][nf][3]);
            }
        }
    }
}

// ---------------- output projection ----------------------------------------
__global__ void __launch_bounds__(128, 2) outproj_tc(
    const float* __restrict__ bo, float* __restrict__ out)
{
    extern __shared__ char sm[];
    float c[4][8][4];
    #pragma unroll
    for (int mf = 0; mf < 4; mf++)
        #pragma unroll
        for (int nf = 0; nf < 8; nf++)
            #pragma unroll
            for (int i = 0; i < 4; i++) c[mf][nf][i] = 0.f;

    int mBase = blockIdx.y * MT, nBase = blockIdx.x * NT;
    gemm_main(g_ch, g_wh[3], mBase, nBase, c, sm);

    int tid = threadIdx.x, lane = tid & 31, warp = tid >> 5;
    int g = lane >> 2, t = lane & 3;
    int wm = (warp & 1) * 64, wn = (warp >> 1) * 64;

    #pragma unroll
    for (int mf = 0; mf < 4; mf++) {
        int m = mBase + wm + mf*16 + g;
        #pragma unroll
        for (int nf = 0; nf < 8; nf++) {
            int n = nBase + wn + nf*8 + 2*t;
            float b0 = bo[n], b1 = bo[n+1];
            float* dst = out + (size_t)m*DIM + n;
            *(float2*)dst           = make_float2(c[mf][nf][0] + b0, c[mf][nf][1] + b1);
            *(float2*)(dst + 8*DIM) = make_float2(c[mf][nf][2] + b0, c[mf][nf][3] + b1);
        }
    }
}

// ---------------- Flash attention: fp16, P kept in registers ---------------
// (unchanged from R14/R15)
#define CK    32
#define QKSTB 144
#define VSTB  80
#define SM_QB 0
#define SM_K0 18432
#define SM_K1 23040
#define SM_V0 27648
#define SM_V1 32768
#define ATTN_SMEM 37888

__global__ void __launch_bounds__(256, 2) attn_tc()
{
    extern __shared__ char sm[];
    char* smc = sm;
    char* Kb[2] = { smc + SM_K0, smc + SM_K1 };
    char* Vb[2] = { smc + SM_V0, smc + SM_V1 };

    int tid = threadIdx.x, lane = tid & 31, warp = tid >> 5;
    int bh = blockIdx.y;
    int qBase = blockIdx.x * 128;
    const char* Qp = (const char*)g_qh + ((size_t)bh*SEQ + qBase)*HD*2;
    const char* Kp = (const char*)g_kh + (size_t)bh*SEQ*HD*2;
    const char* Vp = (const char*)(g_vh + (size_t)bh*SEQ*HD);   // [hd][s] fp16

    // prologue: Q (16KB) + K0 (4KB) + V0 (4KB)
    #pragma unroll
    for (int i = 0; i < 4; i++) {
        int idx = tid + i*256;
        int r = idx >> 3, c = (idx & 7) << 4;
        CPA16(smaddr(smc + SM_QB + r*QKSTB + c), Qp + r*128 + c);
    }
    {
        int r = tid >> 3, c = (tid & 7) << 4;
        CPA16(smaddr(Kb[0] + r*QKSTB + c), Kp + r*128 + c);
    }
    {
        int r = tid >> 2, c = (tid & 3) << 4;
        CPA16(smaddr(Vb[0] + r*VSTB + c), Vp + (size_t)r*SEQ*2 + c);
    }
    CPA_COMMIT();

    int wq = warp * 16;
    int l15 = lane & 15, lh = (lane >> 4) << 4;
    int g = lane >> 2, t = lane & 3;
    int qr = wq + g;

    float o[8][4];
    #pragma unroll
    for (int nf = 0; nf < 8; nf++)
        #pragma unroll
        for (int i = 0; i < 4; i++) o[nf][i] = 0.f;
    float sum0 = 0.f, sum1 = 0.f;

    CPA_WAIT(0);
    __syncthreads();
    uint32_t qf[4][4];
    #pragma unroll
    for (int ksl = 0; ksl < 4; ksl++)
        ldsm4(qf[ksl][0], qf[ksl][1], qf[ksl][2], qf[ksl][3],
              smaddr(smc + SM_QB + (wq + l15)*QKSTB + lh + ksl*32));

    const int nIt = SEQ / CK;   // 64
    for (int it = 0; it < nIt; it++) {
        if (it > 0) { CPA_WAIT(0); __syncthreads(); }
        if (it + 1 < nIt) {
            int kc = (it + 1) * CK;
            int st = (it + 1) & 1;
            {
                int r = tid >> 3, c = (tid & 7) << 4;
                CPA16(smaddr(Kb[st] + r*QKSTB + c), Kp + (size_t)(kc + r)*128 + c);
            }
            {
                int r = tid >> 2, c = (tid & 3) << 4;
                CPA16(smaddr(Vb[st] + r*VSTB + c), Vp + ((size_t)r*SEQ + kc)*2 + c);
            }
            CPA_COMMIT();
        }
        char* kb_ = Kb[it & 1];
        char* vb_ = Vb[it & 1];

        // GEMM1 (fp16): S(16q x 32k) = Q * K^T -- 8 ldsm + 16 mma
        float s[4][4];
        #pragma unroll
        for (int nf = 0; nf < 4; nf++)
            #pragma unroll
            for (int i = 0; i < 4; i++) s[nf][i] = 0.f;
        #pragma unroll
        for (int ksl = 0; ksl < 4; ksl++) {
            #pragma unroll
            for (int p = 0; p < 2; p++) {
                uint32_t k0, k1, k2, k3;
                ldsm4(k0, k1, k2, k3,
                      smaddr(kb_ + (p*16 + l15)*QKSTB + lh + ksl*32));
                mma16(s[2*p],   qf[ksl][0], qf[ksl][1], qf[ksl][2], qf[ksl][3], k0, k2);
                mma16(s[2*p+1], qf[ksl][0], qf[ksl][1], qf[ksl][2], qf[ksl][3], k1, k3);
            }
        }

        // softmax numerators p = 2^s, packed DIRECTLY into GEMM2 A-fragments.
        uint32_t pa[2][4];
        #pragma unroll
        for (int nf = 0; nf < 4; nf++) {
            float p0 = ex2(s[nf][0]);
            float p1 = ex2(s[nf][1]);
            float p2 = ex2(s[nf][2]);
            float p3 = ex2(s[nf][3]);
            sum0 += p0 + p1;  sum1 += p2 + p3;
            pa[nf >> 1][(nf & 1) ? 2 : 0] = pack_f16(p0, p1);   // row g
            pa[nf >> 1][(nf & 1) ? 3 : 1] = pack_f16(p2, p3);   // row g+8
        }

        // GEMM2 (fp16): O(16q x 64hd) += P(16x32) * V(32x64) -- 8 ldsm + 16 mma
        #pragma unroll
        for (int kh = 0; kh < 2; kh++) {
            #pragma unroll
            for (int p = 0; p < 4; p++) {
                uint32_t v0, v1, v2, v3;
                ldsm4(v0, v1, v2, v3,
                      smaddr(vb_ + (p*16 + l15)*VSTB + kh*32 + lh));
                mma16(o[2*p],   pa[kh][0], pa[kh][1], pa[kh][2], pa[kh][3], v0, v2);
                mma16(o[2*p+1], pa[kh][0], pa[kh][1], pa[kh][2], pa[kh][3], v1, v3);
            }
        }
    }

    // final row-sum reduction over the lane quad
    sum0 += __shfl_xor_sync(0xffffffffu, sum0, 1);
    sum0 += __shfl_xor_sync(0xffffffffu, sum0, 2);
    sum1 += __shfl_xor_sync(0xffffffffu, sum1, 1);
    sum1 += __shfl_xor_sync(0xffffffffu, sum1, 2);

    int b = bh >> 4, h = bh & 15;
    float inv0 = 1.0f / sum0, inv1 = 1.0f / sum1;
    int q0 = qBase + qr;
    #pragma unroll
    for (int nf = 0; nf < 8; nf++) {
        int col = nf*8 + 2*t;
        uint32_t* d0 = g_ch + (((size_t)(b*SEQ + q0))*DIM + h*HD + col) / 2;
        d0[0]         = pack_f16(o[nf][0]*inv0, o[nf][1]*inv0);
        d0[4*DIM]     = pack_f16(o[nf][2]*inv1, o[nf][3]*inv1);   // row q0+8
    }
}

// ---------------- launch ----------------------------------------------------
extern "C" void kernel_launch(void* const* d_in, const int* in_sizes, int n_in,
                              void* d_out, int out_size)
{
    const float* x  = (const float*)d_in[0];
    const float* wq = (const float*)d_in[1];
    const float* wk = (const float*)d_in[2];
    const float* wv = (const float*)d_in[3];
    const float* wo = (const float*)d_in[4];
    const float* bo = (const float*)d_in[5];
    float* out = (float*)d_out;

    cvt_kernel<<<dim3((MTOT*DIM/4 + 255)/256, 5), 256>>>(x, wq, wk, wv, wo);

    cudaFuncSetAttribute(qkv_tc, cudaFuncAttributeMaxDynamicSharedMemorySize, PROJ_SMEM);
    qkv_tc<<<dim3(DIM/NT, MTOT/MT, 3), 128, PROJ_SMEM>>>();

    cudaFuncSetAttribute(attn_tc, cudaFuncAttributeMaxDynamicSharedMemorySize, ATTN_SMEM);
    attn_tc<<<dim3(SEQ/128, BATCH*NH), 256, ATTN_SMEM>>>();

    cudaFuncSetAttribute(outproj_tc, cudaFuncAttributeMaxDynamicSharedMemorySize, PROJ_SMEM);
    outproj_tc<<<dim3(DIM/NT, MTOT/MT), 128, PROJ_SMEM>>>(bo, out);
}